// round 7
// baseline (speedup 1.0000x reference)
#include <cuda_runtime.h>

#define NPTS 16384
#define KNB  16

typedef unsigned long long u64;

// Scratch (no allocations allowed).
__device__ __align__(16) float g_A[NPTS * 128];
__device__ int g_nbr[NPTS * KNB];
__device__ __align__(16) float4 g_pos4[NPTS];

// ---------------------------------------------------------------------------
// Packed f32x2 helpers.
// ---------------------------------------------------------------------------
__device__ __forceinline__ u64 fdup(float x) {
    u64 r; asm("mov.b64 %0, {%1, %1};" : "=l"(r) : "f"(x)); return r;
}
__device__ __forceinline__ u64 fpack(float lo, float hi) {
    u64 r; asm("mov.b64 %0, {%1, %2};" : "=l"(r) : "f"(lo), "f"(hi)); return r;
}
__device__ __forceinline__ u64 mul2(u64 a, u64 b) {
    u64 r; asm("mul.rn.f32x2 %0, %1, %2;" : "=l"(r) : "l"(a), "l"(b)); return r;
}
__device__ __forceinline__ u64 add2(u64 a, u64 b) {
    u64 r; asm("add.rn.f32x2 %0, %1, %2;" : "=l"(r) : "l"(a), "l"(b)); return r;
}
__device__ __forceinline__ u64 fma2v(u64 a, u64 b, u64 c) {
    u64 r; asm("fma.rn.f32x2 %0, %1, %2, %3;" : "=l"(r) : "l"(a), "l"(b), "l"(c)); return r;
}
__device__ __forceinline__ void fma2(u64& d, u64 a, u64 b) {
    asm("fma.rn.f32x2 %0, %1, %2, %0;" : "+l"(d) : "l"(a), "l"(b));
}
__device__ __forceinline__ float2 u2f(u64 v) {
    float2 r; asm("mov.b64 {%0, %1}, %2;" : "=f"(r.x), "=f"(r.y) : "l"(v)); return r;
}

// ---------------------------------------------------------------------------
// Pack pos -> float4 (x,y,z,|p|^2) once.
// ---------------------------------------------------------------------------
__global__ void pos4_kernel(const float* __restrict__ pos) {
    const int i = blockIdx.x * blockDim.x + threadIdx.x;
    const float x = pos[3 * i], y = pos[3 * i + 1], z = pos[3 * i + 2];
    g_pos4[i] = make_float4(x, y, z, x * x + y * y + z * z);
}

// ---------------------------------------------------------------------------
// Warp-cooperative bitonic helpers on packed u64 keys.
// ---------------------------------------------------------------------------
__device__ __forceinline__ u64 sort32(u64 v, int lane) {
#pragma unroll
    for (int k = 2; k <= 32; k <<= 1) {
#pragma unroll
        for (int j = k >> 1; j > 0; j >>= 1) {
            const u64 o = __shfl_xor_sync(0xffffffffu, v, j);
            const bool keepMin = (((lane & j) == 0) == ((lane & k) == 0));
            v = ((v < o) == keepMin) ? v : o;
        }
    }
    return v;
}

__device__ __forceinline__ u64 merge_lower(u64 a, u64 b, int lane) {
    const u64 br = __shfl_sync(0xffffffffu, b, 31 - lane);
    u64 m = (a < br) ? a : br;
#pragma unroll
    for (int j = 16; j > 0; j >>= 1) {
        const u64 o = __shfl_xor_sync(0xffffffffu, m, j);
        const bool keepMin = ((lane & j) == 0);
        m = ((m < o) == keepMin) ? m : o;
    }
    return m;
}

__device__ __forceinline__ void flush_merge(u64& v, float& kthf,
                                            const u64* buf, int cnt, int lane) {
    __syncwarp();
    u64 b0 = (lane < cnt) ? buf[lane] : ~0ull;
    b0 = sort32(b0, lane);
    if (cnt > 32) {
        u64 b1 = (32 + lane < cnt) ? buf[32 + lane] : ~0ull;
        b1 = sort32(b1, lane);
        b0 = merge_lower(b0, b1, lane);
    }
    v = merge_lower(v, b0, lane);
    const unsigned m = (unsigned)(__shfl_sync(0xffffffffu, v, 15) >> 32);
    kthf = (m & 0x80000000u) ? __uint_as_float(m & 0x7fffffffu)
                             : __uint_as_float(~m);
}

// ---------------------------------------------------------------------------
// KNN R7: 2 candidates per lane via f32x2 (pair-SoA smem tile). Hot path:
// 2 LDS.128 + 5 packed ops + 1 unpack + 2 setp + ballot. The per-half d2
// operation sequence is bit-identical to the scalar chain. Hits go through
// exact packed-key compaction + bitonic flush.
// ---------------------------------------------------------------------------
#define WPB  16
#define TILE 1024
#define PAIRS (TILE / 2)
#define SENTINEL 0xFF7FFFFFFFFFFFFFull   // maps back to +FLT_MAX

__global__ void __launch_bounds__(32 * WPB) knn_kernel() {
    __shared__ __align__(16) ulonglong2 s_xy[PAIRS];  // (cx2, cy2)
    __shared__ __align__(16) ulonglong2 s_zw[PAIRS];  // (cz2, cw2)
    __shared__ u64 s_buf[WPB][64];

    const int lane = threadIdx.x & 31;
    const int w    = threadIdx.x >> 5;
    const int row  = blockIdx.x * WPB + w;
    const float4 p = g_pos4[row];
    const u64 px2 = fdup(p.x), py2 = fdup(p.y), pz2 = fdup(p.z), pw2 = fdup(p.w);
    const u64 n2  = fdup(-2.0f);

    u64 v = SENTINEL;
    float kthf = 3.402823466e38f;
    int cnt = 0;

    for (int base = 0; base < NPTS; base += TILE) {
        __syncthreads();
        {
            const int pp = threadIdx.x;            // 512 threads = PAIRS
            const float4 c0 = g_pos4[base + 2 * pp];
            const float4 c1 = g_pos4[base + 2 * pp + 1];
            ulonglong2 xy, zw;
            xy.x = fpack(c0.x, c1.x); xy.y = fpack(c0.y, c1.y);
            zw.x = fpack(c0.z, c1.z); zw.y = fpack(c0.w, c1.w);
            s_xy[pp] = xy; s_zw[pp] = zw;
        }
        __syncthreads();
#pragma unroll 4
        for (int it = 0; it < PAIRS; it += 32) {
            const int pi = it + lane;
            const ulonglong2 xy = s_xy[pi];
            const ulonglong2 zw = s_zw[pi];
            // per-half: dot = fma(px, cx, fma(py, cy, pz*cz)); d2 = fma(-2, dot, pw+cw)
            u64 t = mul2(pz2, zw.x);
            t = fma2v(py2, xy.y, t);
            t = fma2v(px2, xy.x, t);
            const u64 s  = add2(pw2, zw.y);
            const float2 d2 = u2f(fma2v(n2, t, s));
            const bool hit = (d2.x < kthf) | (d2.y < kthf);
            if (__ballot_sync(0xffffffffu, hit)) {
                const int j0 = base + 2 * pi;
                // lo half
                {
                    const bool pr = d2.x < kthf;
                    const unsigned bal = __ballot_sync(0xffffffffu, pr);
                    if (pr) {
                        unsigned u = __float_as_uint(d2.x);
                        u = (u & 0x80000000u) ? ~u : (u | 0x80000000u);
                        s_buf[w][cnt + __popc(bal & ((1u << lane) - 1u))] =
                            ((u64)u << 32) | (unsigned)j0;
                    }
                    cnt += __popc(bal);
                    if (cnt > 32) { flush_merge(v, kthf, s_buf[w], cnt, lane); cnt = 0; }
                }
                // hi half
                {
                    const bool pr = d2.y < kthf;
                    const unsigned bal = __ballot_sync(0xffffffffu, pr);
                    if (pr) {
                        unsigned u = __float_as_uint(d2.y);
                        u = (u & 0x80000000u) ? ~u : (u | 0x80000000u);
                        s_buf[w][cnt + __popc(bal & ((1u << lane) - 1u))] =
                            ((u64)u << 32) | (unsigned)(j0 + 1);
                    }
                    cnt += __popc(bal);
                    if (cnt > 32) { flush_merge(v, kthf, s_buf[w], cnt, lane); cnt = 0; }
                }
            }
        }
    }
    if (cnt) flush_merge(v, kthf, s_buf[w], cnt, lane);
    if (lane < KNB) g_nbr[row * KNB + lane] = (int)(v & 0xFFFFFFFFull);
}

// ---------------------------------------------------------------------------
// Node projection (unchanged).
// ---------------------------------------------------------------------------
template <int CIN, int C, bool FIRST>
__global__ void __launch_bounds__(128) proj_kernel(const float* __restrict__ x,
                                                   const float* __restrict__ pos,
                                                   const float* __restrict__ nrm,
                                                   const float* __restrict__ Wa,
                                                   const float* __restrict__ ba) {
    constexpr int TPN = C / 4;
    __shared__ __align__(16) float sW[CIN * C];
    __shared__ __align__(16) float sb[C];
    const int t = threadIdx.x;
    for (int i = t; i < CIN * C; i += 128) sW[i] = Wa[i];
    for (int i = t; i < C; i += 128) sb[i] = ba[i];
    __syncthreads();

    const int n  = blockIdx.x * (128 / TPN) + t / TPN;
    const int c0 = (t % TPN) * 4;
    float4 acc = *reinterpret_cast<const float4*>(&sb[c0]);
#pragma unroll
    for (int k = 0; k < CIN; ++k) {
        float xv;
        if (FIRST) xv = (k < 3) ? pos[n * 3 + k] : nrm[n * 3 + (k - 3)];
        else       xv = x[n * CIN + k];
        const float4 wv = *reinterpret_cast<const float4*>(&sW[k * C + c0]);
        acc.x = fmaf(xv, wv.x, acc.x);
        acc.y = fmaf(xv, wv.y, acc.y);
        acc.z = fmaf(xv, wv.z, acc.z);
        acc.w = fmaf(xv, wv.w, acc.w);
    }
    *reinterpret_cast<float4*>(&g_A[n * C + c0]) = acc;
}

// ---------------------------------------------------------------------------
// Fused edge kernel (unchanged from R6-passing 623us version).
// ---------------------------------------------------------------------------
template <int C, int G, int NPB>
__global__ void __launch_bounds__(2 * C) edge_kernel(
    const float* __restrict__ pos,
    const float* __restrict__ Wa, int cin_node,
    const float* __restrict__ gmm, const float* __restrict__ bta,
    const float* __restrict__ Wb,  const float* __restrict__ bb,
    float* __restrict__ out) {
    constexpr int B  = 2 * C;
    constexpr int HS = 20;
    constexpr int NG = 4;
    extern __shared__ float smem[];
    float* s_Wb   = smem;
    float* s_H    = s_Wb + C * C;
    float* s_Wrel = s_H + NG * C * HS;
    float* s_g    = s_Wrel + 3 * C;
    float* s_b    = s_g + C;
    float* s_bb   = s_b + C;

    const int t = threadIdx.x;
    for (int i = t; i < C * C; i += B) s_Wb[i] = Wb[i];
    for (int i = t; i < 3 * C; i += B) s_Wrel[i] = Wa[cin_node * C + i];
    for (int i = t; i < C; i += B) { s_g[i] = gmm[i]; s_b[i] = bta[i]; s_bb[i] = bb[i]; }
    __syncthreads();

    const int e    = t & 15;
    const int g    = t >> 4;
    const int lane = t & 31;
    const int w    = t >> 5;
    const int et   = lane & 3;
    const int fi   = lane >> 2;
    const int q3   = (C == 128) ? (w >> 1) : w;
    const int f0   = ((C == 128) ? (w & 1) * 64 : 0) + fi * 8;

    for (int s0 = 0; s0 < NPB; s0 += NG) {
#pragma unroll
        for (int q = 0; q < NG; ++q) {
            const int i = blockIdx.x * NPB + s0 + q;
            float* Hq = s_H + q * C * HS;
            const int j = g_nbr[i * KNB + e];
            const float rx = pos[j * 3 + 0] - pos[i * 3 + 0];
            const float ry = pos[j * 3 + 1] - pos[i * 3 + 1];
            const float rz = pos[j * 3 + 2] - pos[i * 3 + 2];
            const int c0 = g * 8;
            const float* Ar = g_A + j * C + c0;
            const float4 a0 = *reinterpret_cast<const float4*>(Ar);
            const float4 a1 = *reinterpret_cast<const float4*>(Ar + 4);
            float h[8] = {a0.x, a0.y, a0.z, a0.w, a1.x, a1.y, a1.z, a1.w};
            float sum = 0.f;
#pragma unroll
            for (int cc = 0; cc < 8; ++cc) {
                const int c = c0 + cc;
                h[cc] = h[cc] + rx * s_Wrel[c] + ry * s_Wrel[C + c] + rz * s_Wrel[2 * C + c];
                sum += h[cc];
            }
            const float mean = sum * 0.125f;
            float vs = 0.f;
#pragma unroll
            for (int cc = 0; cc < 8; ++cc) { const float d = h[cc] - mean; vs = fmaf(d, d, vs); }
            const float inv = rsqrtf(fmaf(vs, 0.125f, 1e-5f));
#pragma unroll
            for (int cc = 0; cc < 8; ++cc) {
                const int c = c0 + cc;
                const float vv = fmaf((h[cc] - mean) * inv, s_g[c], s_b[c]);
                Hq[c * HS + e] = fmaxf(vv, 0.f);
            }
        }
        __syncthreads();
        {
            const int i = blockIdx.x * NPB + s0 + q3;
            const float* Hq = s_H + q3 * C * HS;
            u64 acc2[4][4];
#pragma unroll
            for (int a = 0; a < 4; ++a)
#pragma unroll
                for (int fp = 0; fp < 4; ++fp) acc2[a][fp] = 0ull;

#pragma unroll 4
            for (int c = 0; c < C; ++c) {
                const float4 h4 = *reinterpret_cast<const float4*>(&Hq[c * HS + et * 4]);
                const ulonglong2 wA = *reinterpret_cast<const ulonglong2*>(&s_Wb[c * C + f0]);
                const ulonglong2 wC = *reinterpret_cast<const ulonglong2*>(&s_Wb[c * C + f0 + 4]);
                const u64 wv[4] = {wA.x, wA.y, wC.x, wC.y};
                const u64 hh[4] = {fdup(h4.x), fdup(h4.y), fdup(h4.z), fdup(h4.w)};
#pragma unroll
                for (int a = 0; a < 4; ++a)
#pragma unroll
                    for (int fp = 0; fp < 4; ++fp)
                        fma2(acc2[a][fp], hh[a], wv[fp]);
            }
            float m[8];
#pragma unroll
            for (int fp = 0; fp < 4; ++fp) {
                const float2 v0 = u2f(acc2[0][fp]);
                const float2 v1 = u2f(acc2[1][fp]);
                const float2 v2 = u2f(acc2[2][fp]);
                const float2 v3 = u2f(acc2[3][fp]);
                m[2 * fp]     = fmaxf(fmaxf(v0.x, v1.x), fmaxf(v2.x, v3.x));
                m[2 * fp + 1] = fmaxf(fmaxf(v0.y, v1.y), fmaxf(v2.y, v3.y));
            }
#pragma unroll
            for (int f = 0; f < 8; ++f) {
                m[f] = fmaxf(m[f], __shfl_xor_sync(0xffffffffu, m[f], 1));
                m[f] = fmaxf(m[f], __shfl_xor_sync(0xffffffffu, m[f], 2));
            }
            if (et == 0) {
                float4 r0, r1;
                r0.x = fmaxf(m[0] + s_bb[f0 + 0], 0.f);
                r0.y = fmaxf(m[1] + s_bb[f0 + 1], 0.f);
                r0.z = fmaxf(m[2] + s_bb[f0 + 2], 0.f);
                r0.w = fmaxf(m[3] + s_bb[f0 + 3], 0.f);
                r1.x = fmaxf(m[4] + s_bb[f0 + 4], 0.f);
                r1.y = fmaxf(m[5] + s_bb[f0 + 5], 0.f);
                r1.z = fmaxf(m[6] + s_bb[f0 + 6], 0.f);
                r1.w = fmaxf(m[7] + s_bb[f0 + 7], 0.f);
                *reinterpret_cast<float4*>(&out[i * C + f0])     = r0;
                *reinterpret_cast<float4*>(&out[i * C + f0 + 4]) = r1;
            }
        }
        __syncthreads();
    }
}

// ---------------------------------------------------------------------------
extern "C" void kernel_launch(void* const* d_in, const int* in_sizes, int n_in,
                              void* d_out, int out_size) {
    const float* pos    = (const float*)d_in[0];
    const float* normal = (const float*)d_in[1];
    const float* W1a = (const float*)d_in[2];
    const float* b1a = (const float*)d_in[3];
    const float* g1  = (const float*)d_in[4];
    const float* be1 = (const float*)d_in[5];
    const float* W1b = (const float*)d_in[6];
    const float* b1b = (const float*)d_in[7];
    const float* W2a = (const float*)d_in[8];
    const float* b2a = (const float*)d_in[9];
    const float* g2  = (const float*)d_in[10];
    const float* be2 = (const float*)d_in[11];
    const float* W2b = (const float*)d_in[12];
    const float* b2b = (const float*)d_in[13];
    const float* W3a = (const float*)d_in[14];
    const float* b3a = (const float*)d_in[15];
    const float* g3  = (const float*)d_in[16];
    const float* be3 = (const float*)d_in[17];
    const float* W3b = (const float*)d_in[18];
    const float* b3b = (const float*)d_in[19];

    float* out = (float*)d_out;
    float* h1 = out;
    float* h2 = out + NPTS * 64;
    float* h3 = out + NPTS * 128;

    const int SMEM64  = (64 * 64  + 4 * 64 * 20  + 3 * 64  + 3 * 64)  * 4;
    const int SMEM128 = (128 * 128 + 4 * 128 * 20 + 3 * 128 + 3 * 128) * 4;
    cudaFuncSetAttribute((const void*)edge_kernel<64, 8, 8>,
                         cudaFuncAttributeMaxDynamicSharedMemorySize, SMEM64);
    cudaFuncSetAttribute((const void*)edge_kernel<128, 16, 8>,
                         cudaFuncAttributeMaxDynamicSharedMemorySize, SMEM128);

    pos4_kernel<<<NPTS / 256, 256>>>(pos);
    knn_kernel<<<NPTS / WPB, 32 * WPB>>>();

    proj_kernel<6, 64, true><<<NPTS / 8, 128>>>(nullptr, pos, normal, W1a, b1a);
    edge_kernel<64, 8, 8><<<NPTS / 8, 128, SMEM64>>>(pos, W1a, 6, g1, be1, W1b, b1b, h1);

    proj_kernel<64, 64, false><<<NPTS / 8, 128>>>(h1, nullptr, nullptr, W2a, b2a);
    edge_kernel<64, 8, 8><<<NPTS / 8, 128, SMEM64>>>(pos, W2a, 64, g2, be2, W2b, b2b, h2);

    proj_kernel<64, 128, false><<<NPTS / 4, 128>>>(h2, nullptr, nullptr, W3a, b3a);
    edge_kernel<128, 16, 8><<<NPTS / 8, 256, SMEM128>>>(pos, W3a, 64, g3, be3, W3b, b3b, h3);
}